// round 8
// baseline (speedup 1.0000x reference)
#include <cuda_runtime.h>
#include <cuda_bf16.h>
#include <stdint.h>
#include <math.h>

// Generator_causal via FP8 (e4m3) mma.sync m16n8k32, fp32 accumulate.
// CTA = 128 rows / 4 warps / 2 m16-tiles per warp, 2 CTAs per SM.
// Per step: fc (K=32, z folded as fp32 epilogue) -> MLP1 -> MLP2 -> dot+sigmoid.
// Inter-layer activations pass through per-warp-private fp8 SMEM tile H.
// Scaling: W*512, xm*64, h*256 (exact powers of 2, undone in epilogues).

#define XD 32
#define HD 128
#define TPB 128
#define ROWS 128

#define SWf  512.f
#define SA0f 64.f
#define SAf  256.f
#define K_FC   (SAf/(SA0f*SWf))   // 1/128
#define K_MLP  (1.f/SWf)          // 1/512
#define K_FIN  (1.f/(SAf*SWf))    // 1/131072

// smem byte offsets
#define OFF_W1F 0          // W1 fp8 B-fragments: 4096 u32 (16KB)
#define OFF_W2F 16384      // W2 fp8 B-fragments (16KB)
#define OFF_WIF 32768      // Wi fp8 B-fragments: 1024 u32 (4KB), restaged per step
#define OFF_H   36864      // h tile: 128 rows x 144B = 18432
#define OFF_ZT  55296      // z bf16 [128][33] (66B rows) = 8448
#define OFF_MB  63744      // M cols bf16x2 pre-scaled by SA0: [32][64B] = 2048
#define OFF_BIS 65792      // bi*SA, double buffered: 2*512
#define OFF_W32 66816      // Wi[:,32]*SA, double buffered: 2*512
#define OFF_WFB 67840      // wf, double buffered: 2*512
#define OFF_B1S 68864      // b1*SA: 512
#define OFF_B2  69376      // b2: 512
#define OFF_BFB 69888      // bf double buffered: 8
#define OFF_SV  69896      // per-row val: 512
#define SMEM_BYTES 70416

static __device__ __forceinline__ void mma_e4m3(float* c, const uint32_t* a,
                                                uint32_t b0, uint32_t b1){
    asm volatile("mma.sync.aligned.m16n8k32.row.col.f32.e4m3.e4m3.f32 "
        "{%0,%1,%2,%3}, {%4,%5,%6,%7}, {%8,%9}, {%0,%1,%2,%3};"
        : "+f"(c[0]), "+f"(c[1]), "+f"(c[2]), "+f"(c[3])
        : "r"(a[0]), "r"(a[1]), "r"(a[2]), "r"(a[3]), "r"(b0), "r"(b1));
}
// u16: low byte = e4m3(lo), high byte = e4m3(hi)
static __device__ __forceinline__ uint32_t pack_e4m3_u16(float hi, float lo){
    uint16_t d;
    asm("cvt.rn.satfinite.e4m3x2.f32 %0, %1, %2;" : "=h"(d) : "f"(hi), "f"(lo));
    return (uint32_t)d;
}
static __device__ __forceinline__ uint32_t pack_bf2(float lo, float hi){
    __nv_bfloat162 p = __floats2bfloat162_rn(lo, hi);
    return *(uint32_t*)&p;
}

// stage step-s params: Wi B-fragments (fp8), bi*SA, w32*SA, wf, bf (scalar buf s&1)
static __device__ __forceinline__ void stage_step(char* base, int t, int s,
    const float* __restrict__ Wi, const float* __restrict__ bi,
    const float* __restrict__ wf, const float* __restrict__ bf)
{
    const int b = s & 1;
    #pragma unroll
    for (int it = 0; it < 8; it++){
        int w = it*TPB + t;                    // 0..1023
        int r = w & 1, l2 = (w>>1)&31, j = w>>6;
        int n = 8*j + (l2>>2);
        int kb = 16*r + 4*(l2&3);
        const float* src = Wi + ((size_t)s*HD + n)*(XD+1) + kb;
        ((uint32_t*)(base+OFF_WIF))[w] =
            pack_e4m3_u16(src[1]*SWf, src[0]*SWf)
          | (pack_e4m3_u16(src[3]*SWf, src[2]*SWf) << 16);
    }
    ((float*)(base+OFF_BIS))[b*HD + t] = bi[s*HD + t] * SAf;
    ((float*)(base+OFF_W32))[b*HD + t] = Wi[((size_t)s*HD + t)*(XD+1) + XD] * SAf;
    ((float*)(base+OFF_WFB))[b*HD + t] = wf[s*HD + t];
    if (t == 0) ((float*)(base+OFF_BFB))[b] = bf[s];
}

__global__ void __launch_bounds__(TPB, 2) gen_causal_fp8(
    const float* __restrict__ x,  const float* __restrict__ z,
    const float* __restrict__ M,  const float* __restrict__ Wi,
    const float* __restrict__ bi, const float* __restrict__ wf,
    const float* __restrict__ bf, const float* __restrict__ W1,
    const float* __restrict__ b1, const float* __restrict__ W2,
    const float* __restrict__ b2, float* __restrict__ out, int B)
{
    extern __shared__ char base[];

    const int t    = threadIdx.x;
    const int lane = t & 31;
    const int warp = t >> 5;
    const int wbase = warp * 32;
    const int tq = lane & 3;
    const int g  = lane >> 2;
    const int ctaRow = blockIdx.x * ROWS;
    const int row = ctaRow + t;
    const bool active = (row < B);

    // ================= one-time init =================
    // W1/W2 -> fp8 B-fragment order: word w = (j*4+kk)*64 + lane*2 + r
    #pragma unroll 4
    for (int it = 0; it < 32; it++){
        int w = it*TPB + t;                    // 0..4095
        int r = w & 1, l2 = (w>>1)&31, jkk = w>>6;
        int n  = 8*(jkk>>2) + (l2>>2);
        int kb = 32*(jkk&3) + 16*r + 4*(l2&3);
        float4 v1 = *(const float4*)(W1 + n*HD + kb);
        float4 v2 = *(const float4*)(W2 + n*HD + kb);
        ((uint32_t*)(base+OFF_W1F))[w] =
            pack_e4m3_u16(v1.y*SWf, v1.x*SWf) | (pack_e4m3_u16(v1.w*SWf, v1.z*SWf) << 16);
        ((uint32_t*)(base+OFF_W2F))[w] =
            pack_e4m3_u16(v2.y*SWf, v2.x*SWf) | (pack_e4m3_u16(v2.w*SWf, v2.z*SWf) << 16);
    }
    // z tile bf16 [128][33]
    #pragma unroll 4
    for (int it = 0; it < 32; it++){
        int idx = it * TPB + t;                // 4096 = 128x32
        int r = idx >> 5, c = idx & 31;
        float v = (ctaRow + r < B) ? z[(size_t)(ctaRow + r)*XD + c] : 0.f;
        __nv_bfloat16 h = __float2bfloat16(v);
        *(uint16_t*)(base + OFF_ZT + r*66 + c*2) = *(uint16_t*)&h;
    }
    // M columns bf16x2 pre-scaled by SA0
    for (int idx = t; idx < 512; idx += TPB){
        int col = idx >> 4, p = idx & 15;
        *(uint32_t*)(base + OFF_MB + col*64 + p*4) =
            pack_bf2(M[(2*p)*XD + col]*SA0f, M[(2*p+1)*XD + col]*SA0f);
    }
    ((float*)(base + OFF_B1S))[t] = b1[t] * SAf;
    ((float*)(base + OFF_B2))[t]  = b2[t];
    stage_step(base, t, 0, Wi, bi, wf, bf);

    // per-row state o as bf16x2
    uint32_t ov[16];
    if (active){
        #pragma unroll
        for (int q = 0; q < 4; q++){
            float4 v = *(const float4*)(x + (size_t)row*XD + 4*q);
            ov[2*q]   = pack_bf2(v.x, v.y);
            ov[2*q+1] = pack_bf2(v.z, v.w);
        }
    } else {
        #pragma unroll
        for (int p = 0; p < 16; p++) ov[p] = 0u;
    }

    char* Hb = base + OFF_H;
    float C[2][16][4];

    for (int i = 0; i < XD; i++){
        const int buf = i & 1;

        // ---- H0: xm*SA0 as fp8, row t, bytes 0..31 ----
        {
            const __nv_bfloat162* mc = (const __nv_bfloat162*)(base + OFF_MB + i*64);
            uint32_t* hrow = (uint32_t*)(Hb + t*144);
            #pragma unroll
            for (int w = 0; w < 8; w++){
                __nv_bfloat162 q0 = __hmul2(*(const __nv_bfloat162*)&ov[2*w],   mc[2*w]);
                __nv_bfloat162 q1 = __hmul2(*(const __nv_bfloat162*)&ov[2*w+1], mc[2*w+1]);
                hrow[w] = pack_e4m3_u16(__high2float(q0), __low2float(q0))
                        | (pack_e4m3_u16(__high2float(q1), __low2float(q1)) << 16);
            }
        }
        __syncthreads();   // (1) H0 + WIF(i) + scalars(i) visible

        #pragma unroll
        for (int m = 0; m < 2; m++)
            #pragma unroll
            for (int j = 0; j < 16; j++)
                #pragma unroll
                for (int q = 0; q < 4; q++) C[m][j][q] = 0.f;

        // ================= fc (K=32) =================
        {
            uint32_t Afc[2][4];
            #pragma unroll
            for (int m = 0; m < 2; m++){
                int rg = wbase + 16*m + g;
                Afc[m][0] = *(const uint32_t*)(Hb + rg*144 + 4*tq);
                Afc[m][1] = *(const uint32_t*)(Hb + (rg+8)*144 + 4*tq);
                Afc[m][2] = *(const uint32_t*)(Hb + rg*144 + 16 + 4*tq);
                Afc[m][3] = *(const uint32_t*)(Hb + (rg+8)*144 + 16 + 4*tq);
            }
            #pragma unroll
            for (int j = 0; j < 16; j++){
                uint2 bv = *(const uint2*)(base + OFF_WIF + j*256 + lane*8);
                mma_e4m3(C[0][j], Afc[0], bv.x, bv.y);
                mma_e4m3(C[1][j], Afc[1], bv.x, bv.y);
            }
        }
        __syncthreads();   // (2) fc reads done -> WIF restageable

        if (i + 1 < XD) stage_step(base, t, i+1, Wi, bi, wf, bf);  // hides behind MLPs

        // ---- fc epilogue: h1*SA = relu(C*K_FC + z*w32*SA + bi*SA) -> fp8 H ----
        {
            float zf[2][2];
            #pragma unroll
            for (int m = 0; m < 2; m++){
                int rg = wbase + 16*m + g;
                zf[m][0] = __bfloat162float(*(const __nv_bfloat16*)(base + OFF_ZT + rg*66 + 2*i));
                zf[m][1] = __bfloat162float(*(const __nv_bfloat16*)(base + OFF_ZT + (rg+8)*66 + 2*i));
            }
            #pragma unroll
            for (int j = 0; j < 16; j++){
                float2 wp = *(const float2*)(base + OFF_W32 + (buf*HD + 8*j + 2*tq)*4);
                float2 bp = *(const float2*)(base + OFF_BIS + (buf*HD + 8*j + 2*tq)*4);
                #pragma unroll
                for (int m = 0; m < 2; m++){
                    int rg = wbase + 16*m + g;
                    float c0 = fmaxf(fmaf(C[m][j][0], K_FC, fmaf(zf[m][0], wp.x, bp.x)), 0.f);
                    float c1 = fmaxf(fmaf(C[m][j][1], K_FC, fmaf(zf[m][0], wp.y, bp.y)), 0.f);
                    float c2 = fmaxf(fmaf(C[m][j][2], K_FC, fmaf(zf[m][1], wp.x, bp.x)), 0.f);
                    float c3 = fmaxf(fmaf(C[m][j][3], K_FC, fmaf(zf[m][1], wp.y, bp.y)), 0.f);
                    *(uint16_t*)(Hb + rg*144 + 8*j + 2*tq)     = (uint16_t)pack_e4m3_u16(c1, c0);
                    *(uint16_t*)(Hb + (rg+8)*144 + 8*j + 2*tq) = (uint16_t)pack_e4m3_u16(c3, c2);
                }
            }
        }
        __syncwarp();

        // ================= MLP1 (W1, K=128) =================
        {
            uint32_t Af[2][4][4];
            #pragma unroll
            for (int m = 0; m < 2; m++){
                int rg = wbase + 16*m + g;
                #pragma unroll
                for (int kk = 0; kk < 4; kk++){
                    Af[m][kk][0] = *(const uint32_t*)(Hb + rg*144 + 32*kk + 4*tq);
                    Af[m][kk][1] = *(const uint32_t*)(Hb + (rg+8)*144 + 32*kk + 4*tq);
                    Af[m][kk][2] = *(const uint32_t*)(Hb + rg*144 + 32*kk + 16 + 4*tq);
                    Af[m][kk][3] = *(const uint32_t*)(Hb + (rg+8)*144 + 32*kk + 16 + 4*tq);
                }
            }
            #pragma unroll
            for (int m = 0; m < 2; m++)
                #pragma unroll
                for (int j = 0; j < 16; j++)
                    #pragma unroll
                    for (int q = 0; q < 4; q++) C[m][j][q] = 0.f;
            #pragma unroll
            for (int j = 0; j < 16; j++){
                #pragma unroll
                for (int kk = 0; kk < 4; kk++){
                    uint2 bv = *(const uint2*)(base + OFF_W1F + (j*4+kk)*256 + lane*8);
                    mma_e4m3(C[0][j], Af[0][kk], bv.x, bv.y);
                    mma_e4m3(C[1][j], Af[1][kk], bv.x, bv.y);
                }
            }
        }
        __syncwarp();   // A loads done before h2 overwrite
        // epi: h2*SA = relu(C*K_MLP + b1*SA) -> fp8 H
        #pragma unroll
        for (int j = 0; j < 16; j++){
            float2 bp = *(const float2*)(base + OFF_B1S + (8*j + 2*tq)*4);
            #pragma unroll
            for (int m = 0; m < 2; m++){
                int rg = wbase + 16*m + g;
                float c0 = fmaxf(fmaf(C[m][j][0], K_MLP, bp.x), 0.f);
                float c1 = fmaxf(fmaf(C[m][j][1], K_MLP, bp.y), 0.f);
                float c2 = fmaxf(fmaf(C[m][j][2], K_MLP, bp.x), 0.f);
                float c3 = fmaxf(fmaf(C[m][j][3], K_MLP, bp.y), 0.f);
                *(uint16_t*)(Hb + rg*144 + 8*j + 2*tq)     = (uint16_t)pack_e4m3_u16(c1, c0);
                *(uint16_t*)(Hb + (rg+8)*144 + 8*j + 2*tq) = (uint16_t)pack_e4m3_u16(c3, c2);
            }
        }
        __syncwarp();

        // ================= MLP2 (W2, K=128) =================
        {
            uint32_t Af[2][4][4];
            #pragma unroll
            for (int m = 0; m < 2; m++){
                int rg = wbase + 16*m + g;
                #pragma unroll
                for (int kk = 0; kk < 4; kk++){
                    Af[m][kk][0] = *(const uint32_t*)(Hb + rg*144 + 32*kk + 4*tq);
                    Af[m][kk][1] = *(const uint32_t*)(Hb + (rg+8)*144 + 32*kk + 4*tq);
                    Af[m][kk][2] = *(const uint32_t*)(Hb + rg*144 + 32*kk + 16 + 4*tq);
                    Af[m][kk][3] = *(const uint32_t*)(Hb + (rg+8)*144 + 32*kk + 16 + 4*tq);
                }
            }
            #pragma unroll
            for (int m = 0; m < 2; m++)
                #pragma unroll
                for (int j = 0; j < 16; j++)
                    #pragma unroll
                    for (int q = 0; q < 4; q++) C[m][j][q] = 0.f;
            #pragma unroll
            for (int j = 0; j < 16; j++){
                #pragma unroll
                for (int kk = 0; kk < 4; kk++){
                    uint2 bv = *(const uint2*)(base + OFF_W2F + (j*4+kk)*256 + lane*8);
                    mma_e4m3(C[0][j], Af[0][kk], bv.x, bv.y);
                    mma_e4m3(C[1][j], Af[1][kk], bv.x, bv.y);
                }
            }
        }

        // ---- final: val = sigmoid( sum relu(C*K_FIN + b2)*wf + bf ) ----
        {
            float bfv = ((const float*)(base + OFF_BFB))[buf];
            #pragma unroll
            for (int m = 0; m < 2; m++){
                float p0 = 0.f, p1 = 0.f;
                #pragma unroll
                for (int j = 0; j < 16; j++){
                    float2 b2v = *(const float2*)(base + OFF_B2 + (8*j + 2*tq)*4);
                    float2 wfv = *(const float2*)(base + OFF_WFB + (buf*HD + 8*j + 2*tq)*4);
                    p0 += fmaxf(fmaf(C[m][j][0], K_FIN, b2v.x), 0.f)*wfv.x
                        + fmaxf(fmaf(C[m][j][1], K_FIN, b2v.y), 0.f)*wfv.y;
                    p1 += fmaxf(fmaf(C[m][j][2], K_FIN, b2v.x), 0.f)*wfv.x
                        + fmaxf(fmaf(C[m][j][3], K_FIN, b2v.y), 0.f)*wfv.y;
                }
                p0 += __shfl_xor_sync(0xFFFFFFFFu, p0, 1);
                p0 += __shfl_xor_sync(0xFFFFFFFFu, p0, 2);
                p1 += __shfl_xor_sync(0xFFFFFFFFu, p1, 1);
                p1 += __shfl_xor_sync(0xFFFFFFFFu, p1, 2);
                if (tq == 0){
                    int lr0 = wbase + 16*m + g;
                    int lr1 = lr0 + 8;
                    float v0 = 1.f/(1.f + __expf(-(p0 + bfv)));
                    float v1 = 1.f/(1.f + __expf(-(p1 + bfv)));
                    ((float*)(base + OFF_SV))[lr0] = v0;
                    ((float*)(base + OFF_SV))[lr1] = v1;
                    int gr0 = ctaRow + lr0, gr1 = ctaRow + lr1;
                    if (gr0 < B) out[(size_t)gr0*XD + i] = v0;
                    if (gr1 < B) out[(size_t)gr1*XD + i] = v1;
                }
            }
        }
        __syncwarp();   // SV visible within warp; MLP2 H reads done before next H0

        // ---- update state o[i] = val (bf16) ----
        {
            float v = ((float*)(base + OFF_SV))[t];
            __nv_bfloat16 vh = __float2bfloat16(v);
            uint32_t vb = (uint32_t)(*(const uint16_t*)&vh);
            #pragma unroll
            for (int p = 0; p < 16; p++){
                if ((i >> 1) == p){
                    ov[p] = (i & 1) ? ((ov[p] & 0x0000FFFFu) | (vb << 16))
                                    : ((ov[p] & 0xFFFF0000u) | vb);
                }
            }
        }
    }
}

extern "C" void kernel_launch(void* const* d_in, const int* in_sizes, int n_in,
                              void* d_out, int out_size) {
    const float* x  = (const float*)d_in[0];
    const float* z  = (const float*)d_in[1];
    const float* M  = (const float*)d_in[2];
    const float* Wi = (const float*)d_in[3];
    const float* bi = (const float*)d_in[4];
    const float* wf = (const float*)d_in[5];
    const float* bf = (const float*)d_in[6];
    const float* W1 = (const float*)d_in[7];
    const float* b1 = (const float*)d_in[8];
    const float* W2 = (const float*)d_in[9];
    const float* b2 = (const float*)d_in[10];
    float* out = (float*)d_out;

    const int B = in_sizes[0] / XD;

    cudaFuncSetAttribute(gen_causal_fp8,
                         cudaFuncAttributeMaxDynamicSharedMemorySize, SMEM_BYTES);

    const int grid = (B + ROWS - 1) / ROWS;
    gen_causal_fp8<<<grid, TPB, SMEM_BYTES>>>(x, z, M, Wi, bi, wf, bf,
                                              W1, b1, W2, b2, out, B);
}

// round 9
// speedup vs baseline: 1.2108x; 1.2108x over previous
#include <cuda_runtime.h>
#include <cuda_bf16.h>
#include <stdint.h>
#include <math.h>

// Generator_causal via bf16 mma.sync, sync-free mainloop.
// Prep kernel pre-bakes Wi/W1/W2 into per-lane B-fragment streams in gmem
// (coalesced LDG, L1-resident). Main kernel: CTA = 128 rows / 4 warps,
// each warp owns 32 rows; o-state in warp-owned smem tile; fc A-fragments
// built directly from o ⊙ M; z folded into fc epilogue (fc K=32).
// NO __syncthreads in the 32-step loop -> warps free-run and de-phase,
// overlapping epilogue (fma/alu) with MMA (tensor) across warps.

#define XD 32
#define HD 128
#define TPB 128
#define ROWS 128

// smem: ZT [128][66B] z bf16 rows; OX [128][80B] o-state bf16 rows; MB [32][64B]
#define OFF_ZT 0
#define OFF_OX 8448
#define OFF_MB 18688
#define SMEM_BYTES 20736

// fragment images in global scratch (built by prep kernel)
__device__ uint2 g_WiF[32*16*2*32];   // [i][j][kk][lane] 256KB
__device__ uint4 g_W1F[16*4*32];      // [j][kkp][lane]   32KB
__device__ uint4 g_W2F[16*4*32];      // 32KB
__device__ float g_w32[32*128];       // Wi[:,32] per step 16KB

static __device__ __forceinline__ uint32_t pack_bf2(float lo, float hi){
    __nv_bfloat162 p = __floats2bfloat162_rn(lo, hi);
    return *(uint32_t*)&p;
}
static __device__ __forceinline__ uint32_t hmul2u(uint32_t a, uint32_t b){
    __nv_bfloat162 r = __hmul2(*(__nv_bfloat162*)&a, *(__nv_bfloat162*)&b);
    return *(uint32_t*)&r;
}
static __device__ __forceinline__ void mma_bf16(float* c, const uint32_t* a,
                                                uint32_t b0, uint32_t b1){
    asm volatile("mma.sync.aligned.m16n8k16.row.col.f32.bf16.bf16.f32 "
        "{%0,%1,%2,%3}, {%4,%5,%6,%7}, {%8,%9}, {%0,%1,%2,%3};"
        : "+f"(c[0]), "+f"(c[1]), "+f"(c[2]), "+f"(c[3])
        : "r"(a[0]), "r"(a[1]), "r"(a[2]), "r"(a[3]), "r"(b0), "r"(b1));
}

// ---------------- prep: bake fragment images ----------------
__global__ void prep_frag(const float* __restrict__ Wi,
                          const float* __restrict__ W1,
                          const float* __restrict__ W2){
    int idx = blockIdx.x * 256 + threadIdx.x;      // 32768 threads
    // WiF: B-frag m16n8k16: reg.x = {B[k0][n],B[k0+1][n]}, reg.y = {B[k0+8],B[k0+9]}
    if (idx < 32*16*2*32){
        int lane = idx & 31, kk = (idx>>5)&1, j = (idx>>6)&15, i = idx>>10;
        int n = 8*j + (lane>>2), k0 = 16*kk + 2*(lane&3);
        const float* s = Wi + ((size_t)i*HD + n)*(XD+1);
        uint2 v;
        v.x = pack_bf2(s[k0],   s[k0+1]);
        v.y = pack_bf2(s[k0+8], s[k0+9]);
        g_WiF[idx] = v;
    }
    if (idx < 16*4*32){
        int lane = idx & 31, kkp = (idx>>5)&3, j = idx>>7;
        int n = 8*j + (lane>>2), kb = 32*kkp + 2*(lane&3);
        const float* s1 = W1 + n*HD;
        const float* s2 = W2 + n*HD;
        uint4 v1, v2;
        v1.x = pack_bf2(s1[kb],    s1[kb+1]);  v1.y = pack_bf2(s1[kb+8],  s1[kb+9]);
        v1.z = pack_bf2(s1[kb+16], s1[kb+17]); v1.w = pack_bf2(s1[kb+24], s1[kb+25]);
        v2.x = pack_bf2(s2[kb],    s2[kb+1]);  v2.y = pack_bf2(s2[kb+8],  s2[kb+9]);
        v2.z = pack_bf2(s2[kb+16], s2[kb+17]); v2.w = pack_bf2(s2[kb+24], s2[kb+25]);
        g_W1F[idx] = v1;
        g_W2F[idx] = v2;
    }
    if (idx < 32*128){
        int i = idx >> 7, n = idx & 127;
        g_w32[idx] = Wi[((size_t)i*HD + n)*(XD+1) + XD];
    }
}

// ---------------- main ----------------
__global__ void __launch_bounds__(TPB, 2) gen_causal_nf(
    const float* __restrict__ x,  const float* __restrict__ z,
    const float* __restrict__ M,
    const float* __restrict__ bi, const float* __restrict__ wf,
    const float* __restrict__ bf,
    const float* __restrict__ b1, const float* __restrict__ b2,
    float* __restrict__ out, int B)
{
    extern __shared__ char base[];
    char* ZTp = base + OFF_ZT;
    char* OXp = base + OFF_OX;
    char* MBp = base + OFF_MB;

    const int t    = threadIdx.x;
    const int lane = t & 31;
    const int warp = t >> 5;
    const int wbase = warp * 32;
    const int tq = lane & 3;
    const int g  = lane >> 2;
    const int ctaRow = blockIdx.x * ROWS;
    const int row = ctaRow + t;
    const bool active = (row < B);

    // ---- one-time init ----
    #pragma unroll 4
    for (int it = 0; it < 32; it++){
        int idx = it * TPB + t;                   // 4096 = 128x32
        int r = idx >> 5, c = idx & 31;
        float v = (ctaRow + r < B) ? z[(size_t)(ctaRow + r)*XD + c] : 0.f;
        __nv_bfloat16 h = __float2bfloat16(v);
        *(uint16_t*)(ZTp + r*66 + c*2) = *(uint16_t*)&h;
    }
    for (int idx = t; idx < 512; idx += TPB){
        int col = idx >> 4, p = idx & 15;
        *(uint32_t*)(MBp + col*64 + p*4) =
            pack_bf2(M[(2*p)*XD + col], M[(2*p+1)*XD + col]);
    }
    {   // o-state row t = x row (bf16)
        uint32_t* oxr = (uint32_t*)(OXp + t*80);
        if (active){
            #pragma unroll
            for (int q = 0; q < 4; q++){
                float4 v = *(const float4*)(x + (size_t)row*XD + 4*q);
                oxr[2*q]   = pack_bf2(v.x, v.y);
                oxr[2*q+1] = pack_bf2(v.z, v.w);
            }
        } else {
            #pragma unroll
            for (int q = 0; q < 8; q++) oxr[q] = 0u;
        }
    }
    __syncthreads();   // the ONLY cta-wide sync

    const int rg0 = wbase + g;        // m=0 rows: rg0, rg0+8
    const int rg1 = wbase + 16 + g;   // m=1 rows

    float    C[2][16][4];
    uint32_t A[2][8][4];

    for (int i = 0; i < XD; i++){
        // ---- M column i (broadcast LDS) ----
        uint32_t mb[16];
        #pragma unroll
        for (int p = 0; p < 16; p++) mb[p] = *(const uint32_t*)(MBp + i*64 + p*4);

        // ---- fc A-frags directly from OX ⊙ M (warp-local rows) ----
        uint32_t afc[2][2][4];
        #pragma unroll
        for (int m = 0; m < 2; m++){
            int rg = m ? rg1 : rg0;
            #pragma unroll
            for (int kk = 0; kk < 2; kk++){
                afc[m][kk][0] = hmul2u(*(const uint32_t*)(OXp + rg*80 + kk*32 + tq*4),        mb[8*kk+tq]);
                afc[m][kk][1] = hmul2u(*(const uint32_t*)(OXp + (rg+8)*80 + kk*32 + tq*4),    mb[8*kk+tq]);
                afc[m][kk][2] = hmul2u(*(const uint32_t*)(OXp + rg*80 + kk*32 + 16 + tq*4),   mb[8*kk+4+tq]);
                afc[m][kk][3] = hmul2u(*(const uint32_t*)(OXp + (rg+8)*80 + kk*32 + 16 + tq*4), mb[8*kk+4+tq]);
            }
        }

        #pragma unroll
        for (int m = 0; m < 2; m++)
            #pragma unroll
            for (int j = 0; j < 16; j++)
                #pragma unroll
                for (int q = 0; q < 4; q++) C[m][j][q] = 0.f;

        // ================= fc (K=32) =================
        {
            const uint2* wif = g_WiF + (size_t)i*16*2*32;
            #pragma unroll
            for (int j = 0; j < 16; j++){
                uint2 w0 = __ldg(&wif[(j*2+0)*32 + lane]);
                uint2 w1 = __ldg(&wif[(j*2+1)*32 + lane]);
                mma_bf16(C[0][j], afc[0][0], w0.x, w0.y);
                mma_bf16(C[0][j], afc[0][1], w1.x, w1.y);
                mma_bf16(C[1][j], afc[1][0], w0.x, w0.y);
                mma_bf16(C[1][j], afc[1][1], w1.x, w1.y);
            }
        }

        // ---- fc epilogue: A = bf16(relu(C + z*w32 + bi)) ----
        {
            float zf[2][2];
            #pragma unroll
            for (int m = 0; m < 2; m++){
                int rg = m ? rg1 : rg0;
                zf[m][0] = __bfloat162float(*(const __nv_bfloat16*)(ZTp + rg*66 + 2*i));
                zf[m][1] = __bfloat162float(*(const __nv_bfloat16*)(ZTp + (rg+8)*66 + 2*i));
            }
            #pragma unroll
            for (int jp = 0; jp < 8; jp++){
                float2 blo = __ldg((const float2*)(bi + i*HD + 16*jp + 2*tq));
                float2 bhi = __ldg((const float2*)(bi + i*HD + 16*jp + 8 + 2*tq));
                float2 wlo = __ldg((const float2*)(g_w32 + i*HD + 16*jp + 2*tq));
                float2 whi = __ldg((const float2*)(g_w32 + i*HD + 16*jp + 8 + 2*tq));
                #pragma unroll
                for (int m = 0; m < 2; m++){
                    float t00 = fmaf(zf[m][0], wlo.x, blo.x);
                    float t01 = fmaf(zf[m][0], wlo.y, blo.y);
                    float t10 = fmaf(zf[m][1], wlo.x, blo.x);
                    float t11 = fmaf(zf[m][1], wlo.y, blo.y);
                    float u00 = fmaf(zf[m][0], whi.x, bhi.x);
                    float u01 = fmaf(zf[m][0], whi.y, bhi.y);
                    float u10 = fmaf(zf[m][1], whi.x, bhi.x);
                    float u11 = fmaf(zf[m][1], whi.y, bhi.y);
                    const float* c0 = C[m][2*jp];
                    const float* c1 = C[m][2*jp+1];
                    A[m][jp][0] = pack_bf2(fmaxf(c0[0]+t00,0.f), fmaxf(c0[1]+t01,0.f));
                    A[m][jp][1] = pack_bf2(fmaxf(c0[2]+t10,0.f), fmaxf(c0[3]+t11,0.f));
                    A[m][jp][2] = pack_bf2(fmaxf(c1[0]+u00,0.f), fmaxf(c1[1]+u01,0.f));
                    A[m][jp][3] = pack_bf2(fmaxf(c1[2]+u10,0.f), fmaxf(c1[3]+u11,0.f));
                }
            }
        }

        // ================= MLP1 (W1, K=128) =================
        #pragma unroll
        for (int m = 0; m < 2; m++)
            #pragma unroll
            for (int j = 0; j < 16; j++)
                #pragma unroll
                for (int q = 0; q < 4; q++) C[m][j][q] = 0.f;
        #pragma unroll
        for (int j = 0; j < 16; j++){
            #pragma unroll
            for (int kkp = 0; kkp < 4; kkp++){
                uint4 bv = __ldg(&g_W1F[(j*4+kkp)*32 + lane]);
                mma_bf16(C[0][j], A[0][2*kkp],   bv.x, bv.y);
                mma_bf16(C[0][j], A[0][2*kkp+1], bv.z, bv.w);
                mma_bf16(C[1][j], A[1][2*kkp],   bv.x, bv.y);
                mma_bf16(C[1][j], A[1][2*kkp+1], bv.z, bv.w);
            }
        }
        // epilogue with b1
        #pragma unroll
        for (int jp = 0; jp < 8; jp++){
            float2 blo = __ldg((const float2*)(b1 + 16*jp + 2*tq));
            float2 bhi = __ldg((const float2*)(b1 + 16*jp + 8 + 2*tq));
            #pragma unroll
            for (int m = 0; m < 2; m++){
                const float* c0 = C[m][2*jp];
                const float* c1 = C[m][2*jp+1];
                A[m][jp][0] = pack_bf2(fmaxf(c0[0]+blo.x,0.f), fmaxf(c0[1]+blo.y,0.f));
                A[m][jp][1] = pack_bf2(fmaxf(c0[2]+blo.x,0.f), fmaxf(c0[3]+blo.y,0.f));
                A[m][jp][2] = pack_bf2(fmaxf(c1[0]+bhi.x,0.f), fmaxf(c1[1]+bhi.y,0.f));
                A[m][jp][3] = pack_bf2(fmaxf(c1[2]+bhi.x,0.f), fmaxf(c1[3]+bhi.y,0.f));
            }
        }

        // ================= MLP2 (W2, K=128) =================
        #pragma unroll
        for (int m = 0; m < 2; m++)
            #pragma unroll
            for (int j = 0; j < 16; j++)
                #pragma unroll
                for (int q = 0; q < 4; q++) C[m][j][q] = 0.f;
        #pragma unroll
        for (int j = 0; j < 16; j++){
            #pragma unroll
            for (int kkp = 0; kkp < 4; kkp++){
                uint4 bv = __ldg(&g_W2F[(j*4+kkp)*32 + lane]);
                mma_bf16(C[0][j], A[0][2*kkp],   bv.x, bv.y);
                mma_bf16(C[0][j], A[0][2*kkp+1], bv.z, bv.w);
                mma_bf16(C[1][j], A[1][2*kkp],   bv.x, bv.y);
                mma_bf16(C[1][j], A[1][2*kkp+1], bv.z, bv.w);
            }
        }

        // ---- final: val = sigmoid( sum relu(C+b2)*wf + bf ); update OX + out ----
        {
            float bfv = __ldg(bf + i);
            #pragma unroll
            for (int m = 0; m < 2; m++){
                float p0 = 0.f, p1 = 0.f;
                #pragma unroll
                for (int j = 0; j < 16; j++){
                    float2 b2v = __ldg((const float2*)(b2 + 8*j + 2*tq));
                    float2 wfv = __ldg((const float2*)(wf + i*HD + 8*j + 2*tq));
                    p0 += fmaxf(C[m][j][0]+b2v.x, 0.f)*wfv.x
                        + fmaxf(C[m][j][1]+b2v.y, 0.f)*wfv.y;
                    p1 += fmaxf(C[m][j][2]+b2v.x, 0.f)*wfv.x
                        + fmaxf(C[m][j][3]+b2v.y, 0.f)*wfv.y;
                }
                p0 += __shfl_xor_sync(0xFFFFFFFFu, p0, 1);
                p0 += __shfl_xor_sync(0xFFFFFFFFu, p0, 2);
                p1 += __shfl_xor_sync(0xFFFFFFFFu, p1, 1);
                p1 += __shfl_xor_sync(0xFFFFFFFFu, p1, 2);
                if (tq == 0){
                    int lr0 = (m ? rg1 : rg0);
                    int lr1 = lr0 + 8;
                    float v0 = 1.f/(1.f + __expf(-(p0 + bfv)));
                    float v1 = 1.f/(1.f + __expf(-(p1 + bfv)));
                    __nv_bfloat16 h0 = __float2bfloat16(v0);
                    __nv_bfloat16 h1 = __float2bfloat16(v1);
                    *(uint16_t*)(OXp + lr0*80 + 2*i) = *(uint16_t*)&h0;
                    *(uint16_t*)(OXp + lr1*80 + 2*i) = *(uint16_t*)&h1;
                    int gr0 = ctaRow + lr0, gr1 = ctaRow + lr1;
                    if (gr0 < B) out[(size_t)gr0*XD + i] = v0;
                    if (gr1 < B) out[(size_t)gr1*XD + i] = v1;
                }
            }
        }
        __syncwarp();   // OX writes visible to this warp's next-step A-frag loads
    }
}

extern "C" void kernel_launch(void* const* d_in, const int* in_sizes, int n_in,
                              void* d_out, int out_size) {
    const float* x  = (const float*)d_in[0];
    const float* z  = (const float*)d_in[1];
    const float* M  = (const float*)d_in[2];
    const float* Wi = (const float*)d_in[3];
    const float* bi = (const float*)d_in[4];
    const float* wf = (const float*)d_in[5];
    const float* bf = (const float*)d_in[6];
    const float* W1 = (const float*)d_in[7];
    const float* b1 = (const float*)d_in[8];
    const float* W2 = (const float*)d_in[9];
    const float* b2 = (const float*)d_in[10];
    float* out = (float*)d_out;

    const int B = in_sizes[0] / XD;

    prep_frag<<<128, 256>>>(Wi, W1, W2);

    cudaFuncSetAttribute(gen_causal_nf,
                         cudaFuncAttributeMaxDynamicSharedMemorySize, SMEM_BYTES);
    const int grid = (B + ROWS - 1) / ROWS;
    gen_causal_nf<<<grid, TPB, SMEM_BYTES>>>(x, z, M, bi, wf, bf,
                                             b1, b2, out, B);
}

// round 10
// speedup vs baseline: 1.2932x; 1.0680x over previous
#include <cuda_runtime.h>
#include <cuda_bf16.h>
#include <stdint.h>
#include <math.h>

// Generator_causal via bf16 mma.sync, sync-free mainloop, j-half restructure.
// Per warp: 32 rows (2 x m16 tiles). Layers computed in two j-halves so only
// half the C accumulators (64 regs) are live -> ptxas can prefetch weight LDGs.
// fc -> A, mlp1 -> A2 (ping-pong), mlp2 consumes A2 into the final dot.
// First MMA of each chain uses a zero-C variant (no 128-reg zero-init).

#define XD 32
#define HD 128
#define TPB 128
#define ROWS 128

// smem: ZT [128][66B] z bf16 rows; OX [128][80B] o-state bf16 rows; MB [32][64B]
#define OFF_ZT 0
#define OFF_OX 8448
#define OFF_MB 18688
#define SMEM_BYTES 20736

// fragment images in global scratch (built by prep kernel)
__device__ uint2 g_WiF[32*16*2*32];   // [i][j][kk][lane] 256KB
__device__ uint4 g_W1F[16*4*32];      // [j][kkp][lane]   32KB
__device__ uint4 g_W2F[16*4*32];      // 32KB
__device__ float g_w32[32*128];       // Wi[:,32] per step 16KB

static __device__ __forceinline__ uint32_t pack_bf2(float lo, float hi){
    __nv_bfloat162 p = __floats2bfloat162_rn(lo, hi);
    return *(uint32_t*)&p;
}
static __device__ __forceinline__ uint32_t hmul2u(uint32_t a, uint32_t b){
    __nv_bfloat162 r = __hmul2(*(__nv_bfloat162*)&a, *(__nv_bfloat162*)&b);
    return *(uint32_t*)&r;
}
static __device__ __forceinline__ void mma_bf16(float* c, const uint32_t* a,
                                                uint32_t b0, uint32_t b1){
    asm volatile("mma.sync.aligned.m16n8k16.row.col.f32.bf16.bf16.f32 "
        "{%0,%1,%2,%3}, {%4,%5,%6,%7}, {%8,%9}, {%0,%1,%2,%3};"
        : "+f"(c[0]), "+f"(c[1]), "+f"(c[2]), "+f"(c[3])
        : "r"(a[0]), "r"(a[1]), "r"(a[2]), "r"(a[3]), "r"(b0), "r"(b1));
}
// zero-accumulator variant: writes C without reading it
static __device__ __forceinline__ void mma_bf16_z(float* c, const uint32_t* a,
                                                  uint32_t b0, uint32_t b1){
    float zz = 0.f;
    asm volatile("mma.sync.aligned.m16n8k16.row.col.f32.bf16.bf16.f32 "
        "{%0,%1,%2,%3}, {%4,%5,%6,%7}, {%8,%9}, {%10,%10,%10,%10};"
        : "=f"(c[0]), "=f"(c[1]), "=f"(c[2]), "=f"(c[3])
        : "r"(a[0]), "r"(a[1]), "r"(a[2]), "r"(a[3]), "r"(b0), "r"(b1), "f"(zz));
}

// ---------------- prep: bake fragment images ----------------
__global__ void prep_frag(const float* __restrict__ Wi,
                          const float* __restrict__ W1,
                          const float* __restrict__ W2){
    int idx = blockIdx.x * 256 + threadIdx.x;      // 32768 threads
    if (idx < 32*16*2*32){
        int lane = idx & 31, kk = (idx>>5)&1, j = (idx>>6)&15, i = idx>>10;
        int n = 8*j + (lane>>2), k0 = 16*kk + 2*(lane&3);
        const float* s = Wi + ((size_t)i*HD + n)*(XD+1);
        uint2 v;
        v.x = pack_bf2(s[k0],   s[k0+1]);
        v.y = pack_bf2(s[k0+8], s[k0+9]);
        g_WiF[idx] = v;
    }
    if (idx < 16*4*32){
        int lane = idx & 31, kkp = (idx>>5)&3, j = idx>>7;
        int n = 8*j + (lane>>2), kb = 32*kkp + 2*(lane&3);
        const float* s1 = W1 + n*HD;
        const float* s2 = W2 + n*HD;
        uint4 v1, v2;
        v1.x = pack_bf2(s1[kb],    s1[kb+1]);  v1.y = pack_bf2(s1[kb+8],  s1[kb+9]);
        v1.z = pack_bf2(s1[kb+16], s1[kb+17]); v1.w = pack_bf2(s1[kb+24], s1[kb+25]);
        v2.x = pack_bf2(s2[kb],    s2[kb+1]);  v2.y = pack_bf2(s2[kb+8],  s2[kb+9]);
        v2.z = pack_bf2(s2[kb+16], s2[kb+17]); v2.w = pack_bf2(s2[kb+24], s2[kb+25]);
        g_W1F[idx] = v1;
        g_W2F[idx] = v2;
    }
    if (idx < 32*128){
        int i = idx >> 7, n = idx & 127;
        g_w32[idx] = Wi[((size_t)i*HD + n)*(XD+1) + XD];
    }
}

// ---------------- main ----------------
__global__ void __launch_bounds__(TPB, 2) gen_causal_nf(
    const float* __restrict__ x,  const float* __restrict__ z,
    const float* __restrict__ M,
    const float* __restrict__ bi, const float* __restrict__ wf,
    const float* __restrict__ bf,
    const float* __restrict__ b1, const float* __restrict__ b2,
    float* __restrict__ out, int B)
{
    extern __shared__ char base[];
    char* ZTp = base + OFF_ZT;
    char* OXp = base + OFF_OX;
    char* MBp = base + OFF_MB;

    const int t    = threadIdx.x;
    const int lane = t & 31;
    const int warp = t >> 5;
    const int wbase = warp * 32;
    const int tq = lane & 3;
    const int g  = lane >> 2;
    const int ctaRow = blockIdx.x * ROWS;
    const int row = ctaRow + t;
    const bool active = (row < B);

    // ---- one-time init ----
    #pragma unroll 4
    for (int it = 0; it < 32; it++){
        int idx = it * TPB + t;                   // 4096 = 128x32
        int r = idx >> 5, c = idx & 31;
        float v = (ctaRow + r < B) ? z[(size_t)(ctaRow + r)*XD + c] : 0.f;
        __nv_bfloat16 h = __float2bfloat16(v);
        *(uint16_t*)(ZTp + r*66 + c*2) = *(uint16_t*)&h;
    }
    for (int idx = t; idx < 512; idx += TPB){
        int col = idx >> 4, p = idx & 15;
        *(uint32_t*)(MBp + col*64 + p*4) =
            pack_bf2(M[(2*p)*XD + col], M[(2*p+1)*XD + col]);
    }
    {   // o-state row t = x row (bf16)
        uint32_t* oxr = (uint32_t*)(OXp + t*80);
        if (active){
            #pragma unroll
            for (int q = 0; q < 4; q++){
                float4 v = *(const float4*)(x + (size_t)row*XD + 4*q);
                oxr[2*q]   = pack_bf2(v.x, v.y);
                oxr[2*q+1] = pack_bf2(v.z, v.w);
            }
        } else {
            #pragma unroll
            for (int q = 0; q < 8; q++) oxr[q] = 0u;
        }
    }
    __syncthreads();   // the ONLY cta-wide sync

    const int rg0 = wbase + g;        // m=0 rows: rg0, rg0+8
    const int rg1 = wbase + 16 + g;   // m=1 rows

    uint32_t A [2][8][4];   // fc output  (mlp1 input)
    uint32_t A2[2][8][4];   // mlp1 output (mlp2 input)

    for (int i = 0; i < XD; i++){
        // ---- M column i (broadcast LDS) ----
        uint32_t mb[16];
        #pragma unroll
        for (int p = 0; p < 16; p++) mb[p] = *(const uint32_t*)(MBp + i*64 + p*4);

        // ---- fc A-frags directly from OX ⊙ M (warp-local rows) ----
        uint32_t afc[2][2][4];
        #pragma unroll
        for (int m = 0; m < 2; m++){
            int rg = m ? rg1 : rg0;
            #pragma unroll
            for (int kk = 0; kk < 2; kk++){
                afc[m][kk][0] = hmul2u(*(const uint32_t*)(OXp + rg*80 + kk*32 + tq*4),          mb[8*kk+tq]);
                afc[m][kk][1] = hmul2u(*(const uint32_t*)(OXp + (rg+8)*80 + kk*32 + tq*4),      mb[8*kk+tq]);
                afc[m][kk][2] = hmul2u(*(const uint32_t*)(OXp + rg*80 + kk*32 + 16 + tq*4),     mb[8*kk+4+tq]);
                afc[m][kk][3] = hmul2u(*(const uint32_t*)(OXp + (rg+8)*80 + kk*32 + 16 + tq*4), mb[8*kk+4+tq]);
            }
        }

        float zf[2][2];
        #pragma unroll
        for (int m = 0; m < 2; m++){
            int rg = m ? rg1 : rg0;
            zf[m][0] = __bfloat162float(*(const __nv_bfloat16*)(ZTp + rg*66 + 2*i));
            zf[m][1] = __bfloat162float(*(const __nv_bfloat16*)(ZTp + (rg+8)*66 + 2*i));
        }

        // ================= fc (K=32), two j-halves =================
        #pragma unroll
        for (int h = 0; h < 2; h++){
            float C8[2][8][4];
            const uint2* wif = g_WiF + (size_t)i*16*2*32;
            #pragma unroll
            for (int jj = 0; jj < 8; jj++){
                int j = 8*h + jj;
                uint2 w0 = __ldg(&wif[(j*2+0)*32 + lane]);
                uint2 w1 = __ldg(&wif[(j*2+1)*32 + lane]);
                mma_bf16_z(C8[0][jj], afc[0][0], w0.x, w0.y);
                mma_bf16 (C8[0][jj], afc[0][1], w1.x, w1.y);
                mma_bf16_z(C8[1][jj], afc[1][0], w0.x, w0.y);
                mma_bf16 (C8[1][jj], afc[1][1], w1.x, w1.y);
            }
            // fc epilogue for jp = 4h..4h+3
            #pragma unroll
            for (int q = 0; q < 4; q++){
                int jp = 4*h + q;
                float2 blo = __ldg((const float2*)(bi + i*HD + 16*jp + 2*tq));
                float2 bhi = __ldg((const float2*)(bi + i*HD + 16*jp + 8 + 2*tq));
                float2 wlo = __ldg((const float2*)(g_w32 + i*HD + 16*jp + 2*tq));
                float2 whi = __ldg((const float2*)(g_w32 + i*HD + 16*jp + 8 + 2*tq));
                #pragma unroll
                for (int m = 0; m < 2; m++){
                    float t00 = fmaf(zf[m][0], wlo.x, blo.x);
                    float t01 = fmaf(zf[m][0], wlo.y, blo.y);
                    float t10 = fmaf(zf[m][1], wlo.x, blo.x);
                    float t11 = fmaf(zf[m][1], wlo.y, blo.y);
                    float u00 = fmaf(zf[m][0], whi.x, bhi.x);
                    float u01 = fmaf(zf[m][0], whi.y, bhi.y);
                    float u10 = fmaf(zf[m][1], whi.x, bhi.x);
                    float u11 = fmaf(zf[m][1], whi.y, bhi.y);
                    const float* c0 = C8[m][2*q];
                    const float* c1 = C8[m][2*q+1];
                    A[m][jp][0] = pack_bf2(fmaxf(c0[0]+t00,0.f), fmaxf(c0[1]+t01,0.f));
                    A[m][jp][1] = pack_bf2(fmaxf(c0[2]+t10,0.f), fmaxf(c0[3]+t11,0.f));
                    A[m][jp][2] = pack_bf2(fmaxf(c1[0]+u00,0.f), fmaxf(c1[1]+u01,0.f));
                    A[m][jp][3] = pack_bf2(fmaxf(c1[2]+u10,0.f), fmaxf(c1[3]+u11,0.f));
                }
            }
        }

        // ================= MLP1 (W1, K=128), two j-halves =================
        #pragma unroll
        for (int h = 0; h < 2; h++){
            float C8[2][8][4];
            #pragma unroll
            for (int jj = 0; jj < 8; jj++){
                int j = 8*h + jj;
                #pragma unroll
                for (int kkp = 0; kkp < 4; kkp++){
                    uint4 bv = __ldg(&g_W1F[(j*4+kkp)*32 + lane]);
                    if (kkp == 0){
                        mma_bf16_z(C8[0][jj], A[0][0], bv.x, bv.y);
                        mma_bf16_z(C8[1][jj], A[1][0], bv.x, bv.y);
                    } else {
                        mma_bf16(C8[0][jj], A[0][2*kkp],   bv.x, bv.y);
                        mma_bf16(C8[1][jj], A[1][2*kkp],   bv.x, bv.y);
                    }
                    mma_bf16(C8[0][jj], A[0][2*kkp+1], bv.z, bv.w);
                    mma_bf16(C8[1][jj], A[1][2*kkp+1], bv.z, bv.w);
                }
            }
            // epilogue with b1 -> A2
            #pragma unroll
            for (int q = 0; q < 4; q++){
                int jp = 4*h + q;
                float2 blo = __ldg((const float2*)(b1 + 16*jp + 2*tq));
                float2 bhi = __ldg((const float2*)(b1 + 16*jp + 8 + 2*tq));
                #pragma unroll
                for (int m = 0; m < 2; m++){
                    const float* c0 = C8[m][2*q];
                    const float* c1 = C8[m][2*q+1];
                    A2[m][jp][0] = pack_bf2(fmaxf(c0[0]+blo.x,0.f), fmaxf(c0[1]+blo.y,0.f));
                    A2[m][jp][1] = pack_bf2(fmaxf(c0[2]+blo.x,0.f), fmaxf(c0[3]+blo.y,0.f));
                    A2[m][jp][2] = pack_bf2(fmaxf(c1[0]+bhi.x,0.f), fmaxf(c1[1]+bhi.y,0.f));
                    A2[m][jp][3] = pack_bf2(fmaxf(c1[2]+bhi.x,0.f), fmaxf(c1[3]+bhi.y,0.f));
                }
            }
        }

        // ================= MLP2 (W2, K=128) + final dot, two j-halves ========
        float p0[2] = {0.f, 0.f}, p1[2] = {0.f, 0.f};
        #pragma unroll
        for (int h = 0; h < 2; h++){
            float C8[2][8][4];
            #pragma unroll
            for (int jj = 0; jj < 8; jj++){
                int j = 8*h + jj;
                #pragma unroll
                for (int kkp = 0; kkp < 4; kkp++){
                    uint4 bv = __ldg(&g_W2F[(j*4+kkp)*32 + lane]);
                    if (kkp == 0){
                        mma_bf16_z(C8[0][jj], A2[0][0], bv.x, bv.y);
                        mma_bf16_z(C8[1][jj], A2[1][0], bv.x, bv.y);
                    } else {
                        mma_bf16(C8[0][jj], A2[0][2*kkp],   bv.x, bv.y);
                        mma_bf16(C8[1][jj], A2[1][2*kkp],   bv.x, bv.y);
                    }
                    mma_bf16(C8[0][jj], A2[0][2*kkp+1], bv.z, bv.w);
                    mma_bf16(C8[1][jj], A2[1][2*kkp+1], bv.z, bv.w);
                }
            }
            // final-dot partial for this half
            #pragma unroll
            for (int jj = 0; jj < 8; jj++){
                int j = 8*h + jj;
                float2 b2v = __ldg((const float2*)(b2 + 8*j + 2*tq));
                float2 wfv = __ldg((const float2*)(wf + i*HD + 8*j + 2*tq));
                #pragma unroll
                for (int m = 0; m < 2; m++){
                    p0[m] += fmaxf(C8[m][jj][0]+b2v.x, 0.f)*wfv.x
                           + fmaxf(C8[m][jj][1]+b2v.y, 0.f)*wfv.y;
                    p1[m] += fmaxf(C8[m][jj][2]+b2v.x, 0.f)*wfv.x
                           + fmaxf(C8[m][jj][3]+b2v.y, 0.f)*wfv.y;
                }
            }
        }

        // ---- sigmoid, state + out update ----
        {
            float bfv = __ldg(bf + i);
            #pragma unroll
            for (int m = 0; m < 2; m++){
                float q0 = p0[m], q1 = p1[m];
                q0 += __shfl_xor_sync(0xFFFFFFFFu, q0, 1);
                q0 += __shfl_xor_sync(0xFFFFFFFFu, q0, 2);
                q1 += __shfl_xor_sync(0xFFFFFFFFu, q1, 1);
                q1 += __shfl_xor_sync(0xFFFFFFFFu, q1, 2);
                if (tq == 0){
                    int lr0 = (m ? rg1 : rg0);
                    int lr1 = lr0 + 8;
                    float v0 = 1.f/(1.f + __expf(-(q0 + bfv)));
                    float v1 = 1.f/(1.f + __expf(-(q1 + bfv)));
                    __nv_bfloat16 h0 = __float2bfloat16(v0);
                    __nv_bfloat16 h1 = __float2bfloat16(v1);
                    *(uint16_t*)(OXp + lr0*80 + 2*i) = *(uint16_t*)&h0;
                    *(uint16_t*)(OXp + lr1*80 + 2*i) = *(uint16_t*)&h1;
                    int gr0 = ctaRow + lr0, gr1 = ctaRow + lr1;
                    if (gr0 < B) out[(size_t)gr0*XD + i] = v0;
                    if (gr1 < B) out[(size_t)gr1*XD + i] = v1;
                }
            }
        }
        __syncwarp();   // OX writes visible to this warp's next-step A-frag loads
    }
}

extern "C" void kernel_launch(void* const* d_in, const int* in_sizes, int n_in,
                              void* d_out, int out_size) {
    const float* x  = (const float*)d_in[0];
    const float* z  = (const float*)d_in[1];
    const float* M  = (const float*)d_in[2];
    const float* Wi = (const float*)d_in[3];
    const float* bi = (const float*)d_in[4];
    const float* wf = (const float*)d_in[5];
    const float* bf = (const float*)d_in[6];
    const float* W1 = (const float*)d_in[7];
    const float* b1 = (const float*)d_in[8];
    const float* W2 = (const float*)d_in[9];
    const float* b2 = (const float*)d_in[10];
    float* out = (float*)d_out;

    const int B = in_sizes[0] / XD;

    prep_frag<<<128, 256>>>(Wi, W1, W2);

    cudaFuncSetAttribute(gen_causal_nf,
                         cudaFuncAttributeMaxDynamicSharedMemorySize, SMEM_BYTES);
    const int grid = (B + ROWS - 1) / ROWS;
    gen_causal_nf<<<grid, TPB, SMEM_BYTES>>>(x, z, M, bi, wf, bf,
                                             b1, b2, out, B);
}